// round 2
// baseline (speedup 1.0000x reference)
#include <cuda_runtime.h>
#include <cuda_fp16.h>
#include <math.h>

// ---------------- problem constants ----------------
#define MPTS   32768
#define NPTS   (MPTS * 8)          // 262144 upsampled points
#define NV     9
#define NC     24
#define NH     120
#define NW     160
#define CPRE   50
#define CIN    (NC + 1 + CPRE)     // 75
#define CHID   24
#define HW     (NH * NW)
#define VHW    (NV * HW)
#define VOXSZ  0.04f
#define TQ     (NPTS / 4)          // 65536 threads in MLP, 4 points each

// ---------------- scratch (device globals; no allocation) ----------------
__device__ __align__(16) __half g_featTh[VHW * NC + 64];  // feats (V,H,W,C) fp16, +pad for span overread
__device__ __align__(16) float  g_features[NPTS * NC];    // per-point mean features
__device__ float  g_z[NPTS];
__device__ double g_red[3];                               // sum(z*pos), sum(z^2*pos), sum(pos)

__constant__ int c_off[8][3] = {
    {0,0,0},{1,0,0},{0,1,0},{0,0,1},{1,1,0},{1,0,1},{0,1,1},{1,1,1}
};

// ---------------- f32x2 helpers ----------------
typedef unsigned long long u64;
__device__ __forceinline__ u64 pack2(float a, float b) {
    u64 r; asm("mov.b64 %0, {%1, %2};" : "=l"(r) : "f"(a), "f"(b)); return r;
}
__device__ __forceinline__ u64 fma2(u64 a, u64 b, u64 c) {
    u64 d; asm("fma.rn.f32x2 %0, %1, %2, %3;" : "=l"(d) : "l"(a), "l"(b), "l"(c)); return d;
}
__device__ __forceinline__ float2 unpack2(u64 v) {
    float2 f; asm("mov.b64 {%0, %1}, %2;" : "=f"(f.x), "=f"(f.y) : "l"(v)); return f;
}

// ---------------- kernel 1: transpose (V,C,H,W) fp32 -> (V,H,W,C) fp16; zero g_red ----------------
__global__ void k_transpose(const float* __restrict__ feats) {
    int tid = blockIdx.x * blockDim.x + threadIdx.x;
    if (tid == 0) { g_red[0] = 0.0; g_red[1] = 0.0; g_red[2] = 0.0; }
    if (tid >= VHW) return;
    int v   = tid / HW;
    int rem = tid - v * HW;
    const float* src = feats + (size_t)v * NC * HW + rem;
    float vals[NC];
#pragma unroll
    for (int c = 0; c < NC; c++) vals[c] = src[(size_t)c * HW];   // coalesced across x
    __half2 h[12];
#pragma unroll
    for (int j = 0; j < 12; j++) h[j] = __floats2half2_rn(vals[2*j], vals[2*j+1]);
    uint4* dst = reinterpret_cast<uint4*>(g_featTh) + (size_t)tid * 3;
    dst[0] = *reinterpret_cast<uint4*>(&h[0]);
    dst[1] = *reinterpret_cast<uint4*>(&h[4]);
    dst[2] = *reinterpret_cast<uint4*>(&h[8]);
}

// ---------------- kernel 2: back-projection + per-point stats ----------------
__global__ __launch_bounds__(256) void k_backproject(
    const int*   __restrict__ pre_coords,   // (M,4) int32
    const float* __restrict__ KRcam,        // (V,1,4,4)
    const float* __restrict__ origin,       // (3,)
    const float* __restrict__ w2ac,         // (1,4,4)
    float*       __restrict__ d_out)        // [out 2N | count N | r_coords 4N]
{
    __shared__ float sKR[NV * 16];
    __shared__ float sW2[12];
    __shared__ float sOrg[3];
    int t = threadIdx.x;
    if (t < NV * 16) sKR[t] = KRcam[t];
    if (t < 12)      sW2[t] = w2ac[t];
    if (t < 3)       sOrg[t] = origin[t];
    __syncthreads();

    int n = blockIdx.x * 256 + t;
    int m = n >> 3, k = n & 7;

    int cx = pre_coords[m * 4 + 1] + c_off[k][0];
    int cy = pre_coords[m * 4 + 2] + c_off[k][1];
    int cz = pre_coords[m * 4 + 3] + c_off[k][2];
    float wx = (float)cx * VOXSZ + sOrg[0];
    float wy = (float)cy * VOXSZ + sOrg[1];
    float wz = (float)cz * VOXSZ + sOrg[2];

    // r_coords
    {
        float4 rc;
        rc.x = sW2[0]*wx + sW2[1]*wy + sW2[2]*wz + sW2[3];
        rc.y = sW2[4]*wx + sW2[5]*wy + sW2[6]*wz + sW2[7];
        rc.z = sW2[8]*wx + sW2[9]*wy + sW2[10]*wz + sW2[11];
        rc.w = 0.0f;
        reinterpret_cast<float4*>(d_out + 3 * NPTS)[n] = rc;
    }

    float a[NC];
#pragma unroll
    for (int j = 0; j < NC; j++) a[j] = 0.f;
    float zsum = 0.f;
    int   cnt  = 0;

    const uint4* fb = reinterpret_cast<const uint4*>(g_featTh);

#pragma unroll 1
    for (int v = 0; v < NV; v++) {
        const float* R = sKR + v * 16;
        float ix = R[0]*wx + R[1]*wy + R[2]*wz  + R[3];
        float iy = R[4]*wx + R[5]*wy + R[6]*wz  + R[7];
        float iz = R[8]*wx + R[9]*wy + R[10]*wz + R[11];
        float sz = (fabsf(iz) > 1e-9f) ? iz : 1e-9f;
        float px = ix / sz;
        float py = iy / sz;
        bool msk = (px >= 0.f) && (px <= (float)(NW - 1)) &&
                   (py >= 0.f) && (py <= (float)(NH - 1)) && (iz > 0.f);
        if (!msk) continue;

        float fx0 = floorf(px), fy0 = floorf(py);
        float ax = px - fx0,    ay = py - fy0;
        int ix0 = (int)fx0,     iy0 = (int)fy0;
        float okx = (ix0 + 1 < NW) ? 1.f : 0.f;
        float oky = (iy0 + 1 < NH) ? 1.f : 0.f;
        int iy1 = min(iy0 + 1, NH - 1);

        float w00 = (1.f - ax) * (1.f - ay);
        float w10 = ax * (1.f - ay) * okx;
        float w01 = (1.f - ax) * ay * oky;
        float w11 = ax * ay * okx * oky;

        // contiguous 96B span covers both x0 and x1 (pixel = 48B in fp16)
        int b_top = ((v * NH + iy0) * NW + ix0) * 3;
        int b_bot = ((v * NH + iy1) * NW + ix0) * 3;

        uint4 Tt[6], Bb[6];
#pragma unroll
        for (int j = 0; j < 6; j++) { Tt[j] = fb[b_top + j]; Bb[j] = fb[b_bot + j]; }
        const __half2* th = reinterpret_cast<const __half2*>(Tt); // [0..11]=x0 ch, [12..23]=x1 ch
        const __half2* bh = reinterpret_cast<const __half2*>(Bb);

#pragma unroll
        for (int j = 0; j < 12; j++) {
            float2 t0 = __half22float2(th[j]);
            float2 t1 = __half22float2(th[j + 12]);
            float2 b0 = __half22float2(bh[j]);
            float2 b1 = __half22float2(bh[j + 12]);
            a[2*j]   += w00*t0.x + w10*t1.x + w01*b0.x + w11*b1.x;
            a[2*j+1] += w00*t0.y + w10*t1.y + w01*b0.y + w11*b1.y;
        }
        zsum += iz;
        cnt  += 1;
    }

    float denom = fmaxf((float)cnt, 1.f);
    float inv   = 1.f / denom;
    float4* fdst = reinterpret_cast<float4*>(g_features) + (size_t)n * 6;
#pragma unroll
    for (int j = 0; j < 6; j++)
        fdst[j] = make_float4(a[4*j]*inv, a[4*j+1]*inv, a[4*j+2]*inv, a[4*j+3]*inv);

    float zv = zsum * inv;
    g_z[n] = zv;
    d_out[2 * NPTS + n] = (float)cnt;

    bool  pos = zv > 0.f;
    float r0 = pos ? zv : 0.f;
    float r1 = pos ? zv * zv : 0.f;
    float r2 = pos ? 1.f : 0.f;
#pragma unroll
    for (int o = 16; o > 0; o >>= 1) {
        r0 += __shfl_down_sync(0xffffffffu, r0, o);
        r1 += __shfl_down_sync(0xffffffffu, r1, o);
        r2 += __shfl_down_sync(0xffffffffu, r2, o);
    }
    __shared__ float s0[8], s1[8], s2[8];
    int w = t >> 5, lane = t & 31;
    if (lane == 0) { s0[w] = r0; s1[w] = r1; s2[w] = r2; }
    __syncthreads();
    if (t == 0) {
        float t0 = 0.f, t1 = 0.f, t2 = 0.f;
#pragma unroll
        for (int i = 0; i < 8; i++) { t0 += s0[i]; t1 += s1[i]; t2 += s2[i]; }
        atomicAdd(&g_red[0], (double)t0);
        atomicAdd(&g_red[1], (double)t1);
        atomicAdd(&g_red[2], (double)t2);
    }
}

// ---------------- kernel 3: z-norm + MLP heads (4 points/thread, f32x2) ----------------
__device__ __forceinline__ void mlp_row(u64* A01, u64* A23, u64 fab, u64 fcd,
                                        const float4* __restrict__ wr) {
#pragma unroll
    for (int q = 0; q < 6; q++) {
        float4 w = wr[q];
        u64 w0 = pack2(w.x, w.x);
        A01[4*q+0] = fma2(fab, w0, A01[4*q+0]); A23[4*q+0] = fma2(fcd, w0, A23[4*q+0]);
        u64 w1 = pack2(w.y, w.y);
        A01[4*q+1] = fma2(fab, w1, A01[4*q+1]); A23[4*q+1] = fma2(fcd, w1, A23[4*q+1]);
        u64 w2 = pack2(w.z, w.z);
        A01[4*q+2] = fma2(fab, w2, A01[4*q+2]); A23[4*q+2] = fma2(fcd, w2, A23[4*q+2]);
        u64 w3 = pack2(w.w, w.w);
        A01[4*q+3] = fma2(fab, w3, A01[4*q+3]); A23[4*q+3] = fma2(fcd, w3, A23[4*q+3]);
    }
}

__global__ __launch_bounds__(128) void k_mlp(
    const float* __restrict__ pre_feat,
    const float* __restrict__ W_sp,
    const float* __restrict__ b_sp,
    const float* __restrict__ W_t,
    const float* __restrict__ b_t,
    const float* __restrict__ W_o,
    const float* __restrict__ b_o,
    float*       __restrict__ d_out)
{
    __shared__ float4 sW[CIN * 6];
    __shared__ float  sWt[CHID], sWo[CHID], sB[CHID];
    int t = threadIdx.x;
    const float4* Wv = reinterpret_cast<const float4*>(W_sp);
    for (int i = t; i < CIN * 6; i += 128) sW[i] = Wv[i];
    if (t < CHID) { sWt[t] = W_t[t]; sWo[t] = W_o[t]; sB[t] = b_sp[t]; }
    __syncthreads();

    double npos  = fmax(g_red[2], 1.0);
    double zmean = g_red[0] / npos;
    double var   = g_red[1] - zmean * zmean * npos;
    float  znorm = (float)sqrt(fmax(var, 0.0)) + 1e-5f;
    float  zmf   = (float)zmean;

    int p0 = blockIdx.x * 128 + t;   // handles points p0 + k*TQ, k=0..3

    u64 A01[CHID], A23[CHID];
#pragma unroll
    for (int j = 0; j < CHID; j++) {
        u64 bb = pack2(sB[j], sB[j]);
        A01[j] = bb; A23[j] = bb;
    }

    // features (channels 0..23)
    const float4* f0 = reinterpret_cast<const float4*>(g_features) + (size_t)p0 * 6;
    const float4* f1 = f0 + (size_t)TQ * 6;
    const float4* f2 = f1 + (size_t)TQ * 6;
    const float4* f3 = f2 + (size_t)TQ * 6;
#pragma unroll
    for (int j4 = 0; j4 < 6; j4++) {
        float4 F0 = f0[j4], F1 = f1[j4], F2 = f2[j4], F3 = f3[j4];
        mlp_row(A01, A23, pack2(F0.x, F1.x), pack2(F2.x, F3.x), sW + (4*j4+0)*6);
        mlp_row(A01, A23, pack2(F0.y, F1.y), pack2(F2.y, F3.y), sW + (4*j4+1)*6);
        mlp_row(A01, A23, pack2(F0.z, F1.z), pack2(F2.z, F3.z), sW + (4*j4+2)*6);
        mlp_row(A01, A23, pack2(F0.w, F1.w), pack2(F2.w, F3.w), sW + (4*j4+3)*6);
    }
    // zn (channel 24)
    {
        float z0 = g_z[p0], z1 = g_z[p0 + TQ], z2 = g_z[p0 + 2*TQ], z3 = g_z[p0 + 3*TQ];
        float n0 = (z0 > 0.f) ? (z0 - zmf) / znorm : 0.f;
        float n1 = (z1 > 0.f) ? (z1 - zmf) / znorm : 0.f;
        float n2 = (z2 > 0.f) ? (z2 - zmf) / znorm : 0.f;
        float n3 = (z3 > 0.f) ? (z3 - zmf) / znorm : 0.f;
        mlp_row(A01, A23, pack2(n0, n1), pack2(n2, n3), sW + NC * 6);
    }
    // pre_feat (channels 25..74)
    {
        const float2* q0 = reinterpret_cast<const float2*>(pre_feat + (size_t)( p0          >> 3) * CPRE);
        const float2* q1 = reinterpret_cast<const float2*>(pre_feat + (size_t)((p0 +   TQ) >> 3) * CPRE);
        const float2* q2 = reinterpret_cast<const float2*>(pre_feat + (size_t)((p0 + 2*TQ) >> 3) * CPRE);
        const float2* q3 = reinterpret_cast<const float2*>(pre_feat + (size_t)((p0 + 3*TQ) >> 3) * CPRE);
#pragma unroll
        for (int i = 0; i < CPRE / 2; i++) {
            float2 g0 = q0[i], g1 = q1[i], g2 = q2[i], g3 = q3[i];
            mlp_row(A01, A23, pack2(g0.x, g1.x), pack2(g2.x, g3.x), sW + (NC + 1 + 2*i + 0) * 6);
            mlp_row(A01, A23, pack2(g0.y, g1.y), pack2(g2.y, g3.y), sW + (NC + 1 + 2*i + 1) * 6);
        }
    }

    // relu + heads
    float bt = b_t[0], bo = b_o[0];
    float ts0 = bt, ts1 = bt, ts2 = bt, ts3 = bt;
    float oc0 = bo, oc1 = bo, oc2 = bo, oc3 = bo;
#pragma unroll
    for (int j = 0; j < CHID; j++) {
        float2 ab = unpack2(A01[j]);
        float2 cd = unpack2(A23[j]);
        float h0 = fmaxf(ab.x, 0.f), h1 = fmaxf(ab.y, 0.f);
        float h2 = fmaxf(cd.x, 0.f), h3 = fmaxf(cd.y, 0.f);
        float wt = sWt[j], wo = sWo[j];
        ts0 += h0 * wt; ts1 += h1 * wt; ts2 += h2 * wt; ts3 += h3 * wt;
        oc0 += h0 * wo; oc1 += h1 * wo; oc2 += h2 * wo; oc3 += h3 * wo;
    }
    float2* out = reinterpret_cast<float2*>(d_out);
    out[p0         ] = make_float2(ts0, oc0);
    out[p0 +   TQ  ] = make_float2(ts1, oc1);
    out[p0 + 2*TQ  ] = make_float2(ts2, oc2);
    out[p0 + 3*TQ  ] = make_float2(ts3, oc3);
}

// ---------------- launch ----------------
extern "C" void kernel_launch(void* const* d_in, const int* in_sizes, int n_in,
                              void* d_out, int out_size)
{
    const float *pre_feat = nullptr, *feats = nullptr, *KRcam = nullptr,
                *origin = nullptr, *w2ac = nullptr, *W_sp = nullptr,
                *b_sp = nullptr, *W_t = nullptr, *b_t = nullptr,
                *W_o = nullptr, *b_o = nullptr;
    const int* pre_coords = nullptr;
    int n24 = 0, n1 = 0;

    for (int i = 0; i < n_in; i++) {
        int s = in_sizes[i];
        const void* p = d_in[i];
        switch (s) {
            case MPTS * CPRE:  pre_feat   = (const float*)p; break;
            case MPTS * 4:     pre_coords = (const int*)p;   break;
            case VHW * NC:     feats      = (const float*)p; break;
            case NV * 16:      KRcam      = (const float*)p; break;
            case 3:            origin     = (const float*)p; break;
            case 16:           w2ac       = (const float*)p; break;
            case CIN * CHID:   W_sp       = (const float*)p; break;
            case 24:
                if (n24 == 0) b_sp = (const float*)p;
                else if (n24 == 1) W_t = (const float*)p;
                else W_o = (const float*)p;
                n24++; break;
            case 1:
                if (n1 == 0) b_t = (const float*)p;
                else b_o = (const float*)p;
                n1++; break;
            default: break;
        }
    }

    k_transpose<<<(VHW + 255) / 256, 256>>>(feats);
    k_backproject<<<NPTS / 256, 256>>>(pre_coords, KRcam, origin, w2ac, (float*)d_out);
    k_mlp<<<TQ / 128, 128>>>(pre_feat, W_sp, b_sp, W_t, b_t, W_o, b_o, (float*)d_out);
}

// round 4
// speedup vs baseline: 1.3188x; 1.3188x over previous
#include <cuda_runtime.h>
#include <cuda_fp16.h>
#include <math.h>

// ---------------- problem constants ----------------
#define MPTS   32768
#define NPTS   (MPTS * 8)          // 262144 upsampled points
#define NV     9
#define NC     24
#define NH     120
#define NW     160
#define CPRE   50
#define CIN    (NC + 1 + CPRE)     // 75
#define CHID   24
#define HW     (NH * NW)
#define VHW    (NV * HW)
#define VOXSZ  0.04f
#define TQ     (NPTS / 4)          // 65536 threads in MLP, 4 points each

// ---------------- scratch (device globals; no allocation) ----------------
__device__ __align__(16) __half g_featTh[VHW * NC + 64];  // feats (V,H,W,C) fp16, +pad
__device__ __align__(16) float  g_features[NPTS * NC];    // per-point mean features
__device__ float  g_z[NPTS];
__device__ double g_red[3];                               // sum(z*pos), sum(z^2*pos), sum(pos)

__constant__ int c_off[8][3] = {
    {0,0,0},{1,0,0},{0,1,0},{0,0,1},{1,1,0},{1,0,1},{0,1,1},{1,1,1}
};

// ---------------- helpers ----------------
typedef unsigned long long u64;
__device__ __forceinline__ u64 pack2(float a, float b) {
    u64 r; asm("mov.b64 %0, {%1, %2};" : "=l"(r) : "f"(a), "f"(b)); return r;
}
__device__ __forceinline__ u64 fma2(u64 a, u64 b, u64 c) {
    u64 d; asm("fma.rn.f32x2 %0, %1, %2, %3;" : "=l"(d) : "l"(a), "l"(b), "l"(c)); return d;
}
__device__ __forceinline__ float2 unpack2(u64 v) {
    float2 f; asm("mov.b64 {%0, %1}, %2;" : "=f"(f.x), "=f"(f.y) : "l"(v)); return f;
}
// u32 (two packed halves) -> float2, pure-register path
__device__ __forceinline__ float2 h2f(unsigned u) {
    float2 f;
    asm("{ .reg .b16 lo, hi;\n\t"
        "  mov.b32 {lo, hi}, %2;\n\t"
        "  cvt.f32.f16 %0, lo;\n\t"
        "  cvt.f32.f16 %1, hi; }"
        : "=f"(f.x), "=f"(f.y) : "r"(u));
    return f;
}

// ---------------- kernel 1: transpose (V,C,H,W) fp32 -> (V,H,W,C) fp16; zero g_red ----------------
// 3 threads per pixel, 8 channels each -> one uint4 store per thread.
__global__ void k_transpose(const float* __restrict__ feats) {
    int tid = blockIdx.x * blockDim.x + threadIdx.x;
    if (tid == 0) { g_red[0] = 0.0; g_red[1] = 0.0; g_red[2] = 0.0; }
    if (tid >= VHW * 3) return;
    int pix = tid / 3;
    int c0  = (tid - pix * 3) * 8;
    int v   = pix / HW;
    int rem = pix - v * HW;
    const float* src = feats + (size_t)v * NC * HW + (size_t)c0 * HW + rem;
    float vals[8];
#pragma unroll
    for (int c = 0; c < 8; c++) vals[c] = src[(size_t)c * HW];   // coalesced across x
    __half2 h[4];
#pragma unroll
    for (int j = 0; j < 4; j++) h[j] = __floats2half2_rn(vals[2*j], vals[2*j+1]);
    reinterpret_cast<uint4*>(g_featTh)[pix * 3 + (c0 >> 3)] = *reinterpret_cast<uint4*>(h);
}

// ---------------- kernel 2: back-projection + per-point stats ----------------
__global__ __launch_bounds__(256) void k_backproject(
    const int*   __restrict__ pre_coords,   // (M,4) int32
    const float* __restrict__ KRcam,        // (V,1,4,4)
    const float* __restrict__ origin,       // (3,)
    const float* __restrict__ w2ac,         // (1,4,4)
    float*       __restrict__ d_out)        // [out 2N | count N | r_coords 4N]
{
    __shared__ float sKR[NV * 16];
    __shared__ float sW2[12];
    __shared__ float sOrg[3];
    int t = threadIdx.x;
    if (t < NV * 16) sKR[t] = KRcam[t];
    if (t < 12)      sW2[t] = w2ac[t];
    if (t < 3)       sOrg[t] = origin[t];
    __syncthreads();

    int n = blockIdx.x * 256 + t;
    int m = n >> 3, k = n & 7;

    int cx = pre_coords[m * 4 + 1] + c_off[k][0];
    int cy = pre_coords[m * 4 + 2] + c_off[k][1];
    int cz = pre_coords[m * 4 + 3] + c_off[k][2];
    float wx = (float)cx * VOXSZ + sOrg[0];
    float wy = (float)cy * VOXSZ + sOrg[1];
    float wz = (float)cz * VOXSZ + sOrg[2];

    // r_coords
    {
        float4 rc;
        rc.x = sW2[0]*wx + sW2[1]*wy + sW2[2]*wz + sW2[3];
        rc.y = sW2[4]*wx + sW2[5]*wy + sW2[6]*wz + sW2[7];
        rc.z = sW2[8]*wx + sW2[9]*wy + sW2[10]*wz + sW2[11];
        rc.w = 0.0f;
        reinterpret_cast<float4*>(d_out + 3 * NPTS)[n] = rc;
    }

    float a[NC];
#pragma unroll
    for (int j = 0; j < NC; j++) a[j] = 0.f;
    float zsum = 0.f;
    int   cnt  = 0;

    const uint4* fb = reinterpret_cast<const uint4*>(g_featTh);

#pragma unroll 1
    for (int v = 0; v < NV; v++) {
        const float* R = sKR + v * 16;
        float ix = R[0]*wx + R[1]*wy + R[2]*wz  + R[3];
        float iy = R[4]*wx + R[5]*wy + R[6]*wz  + R[7];
        float iz = R[8]*wx + R[9]*wy + R[10]*wz + R[11];
        float sz = (fabsf(iz) > 1e-9f) ? iz : 1e-9f;
        float px = ix / sz;
        float py = iy / sz;
        bool msk = (px >= 0.f) && (px <= (float)(NW - 1)) &&
                   (py >= 0.f) && (py <= (float)(NH - 1)) && (iz > 0.f);
        if (!msk) continue;

        float fx0 = floorf(px), fy0 = floorf(py);
        float ax = px - fx0,    ay = py - fy0;
        int ix0 = (int)fx0,     iy0 = (int)fy0;
        float okx = (ix0 + 1 < NW) ? 1.f : 0.f;
        float oky = (iy0 + 1 < NH) ? 1.f : 0.f;
        int iy1 = min(iy0 + 1, NH - 1);

        float w00 = (1.f - ax) * (1.f - ay);
        float w10 = ax * (1.f - ay) * okx;
        float w01 = (1.f - ax) * ay * oky;
        float w11 = ax * ay * okx * oky;

        // contiguous 96B span covers both x0 and x1 (pixel = 48B fp16)
        int b_top = ((v * NH + iy0) * NW + ix0) * 3;
        int b_bot = ((v * NH + iy1) * NW + ix0) * 3;

#pragma unroll
        for (int j = 0; j < 6; j++) {
            uint4 T = fb[b_top + j];
            uint4 B = fb[b_bot + j];
            // j<3 -> pixel x0 (weights w00/w01), j>=3 -> pixel x1 (weights w10/w11)
            float wT = (j < 3) ? w00 : w10;
            float wB = (j < 3) ? w01 : w11;
            int   cb = (j < 3) ? (8 * j) : (8 * (j - 3));
            float2 t0 = h2f(T.x), t1 = h2f(T.y), t2 = h2f(T.z), t3 = h2f(T.w);
            float2 u0 = h2f(B.x), u1 = h2f(B.y), u2 = h2f(B.z), u3 = h2f(B.w);
            a[cb+0] += wT*t0.x + wB*u0.x;  a[cb+1] += wT*t0.y + wB*u0.y;
            a[cb+2] += wT*t1.x + wB*u1.x;  a[cb+3] += wT*t1.y + wB*u1.y;
            a[cb+4] += wT*t2.x + wB*u2.x;  a[cb+5] += wT*t2.y + wB*u2.y;
            a[cb+6] += wT*t3.x + wB*u3.x;  a[cb+7] += wT*t3.y + wB*u3.y;
        }
        zsum += iz;
        cnt  += 1;
    }

    float denom = fmaxf((float)cnt, 1.f);
    float inv   = 1.f / denom;
    float4* fdst = reinterpret_cast<float4*>(g_features) + (size_t)n * 6;
#pragma unroll
    for (int j = 0; j < 6; j++)
        fdst[j] = make_float4(a[4*j]*inv, a[4*j+1]*inv, a[4*j+2]*inv, a[4*j+3]*inv);

    float zv = zsum * inv;
    g_z[n] = zv;
    d_out[2 * NPTS + n] = (float)cnt;

    bool  pos = zv > 0.f;
    float r0 = pos ? zv : 0.f;
    float r1 = pos ? zv * zv : 0.f;
    float r2 = pos ? 1.f : 0.f;
#pragma unroll
    for (int o = 16; o > 0; o >>= 1) {
        r0 += __shfl_down_sync(0xffffffffu, r0, o);
        r1 += __shfl_down_sync(0xffffffffu, r1, o);
        r2 += __shfl_down_sync(0xffffffffu, r2, o);
    }
    __shared__ float s0[8], s1[8], s2[8];
    int w = t >> 5, lane = t & 31;
    if (lane == 0) { s0[w] = r0; s1[w] = r1; s2[w] = r2; }
    __syncthreads();
    if (t == 0) {
        float t0 = 0.f, t1 = 0.f, t2 = 0.f;
#pragma unroll
        for (int i = 0; i < 8; i++) { t0 += s0[i]; t1 += s1[i]; t2 += s2[i]; }
        atomicAdd(&g_red[0], (double)t0);
        atomicAdd(&g_red[1], (double)t1);
        atomicAdd(&g_red[2], (double)t2);
    }
}

// ---------------- kernel 3: z-norm + MLP heads (4 points/thread, f32x2) ----------------
__device__ __forceinline__ void mlp_row(u64* A01, u64* A23, u64 fab, u64 fcd,
                                        const float4* __restrict__ wr) {
#pragma unroll
    for (int q = 0; q < 6; q++) {
        float4 w = wr[q];
        u64 w0 = pack2(w.x, w.x);
        A01[4*q+0] = fma2(fab, w0, A01[4*q+0]); A23[4*q+0] = fma2(fcd, w0, A23[4*q+0]);
        u64 w1 = pack2(w.y, w.y);
        A01[4*q+1] = fma2(fab, w1, A01[4*q+1]); A23[4*q+1] = fma2(fcd, w1, A23[4*q+1]);
        u64 w2 = pack2(w.z, w.z);
        A01[4*q+2] = fma2(fab, w2, A01[4*q+2]); A23[4*q+2] = fma2(fcd, w2, A23[4*q+2]);
        u64 w3 = pack2(w.w, w.w);
        A01[4*q+3] = fma2(fab, w3, A01[4*q+3]); A23[4*q+3] = fma2(fcd, w3, A23[4*q+3]);
    }
}

__global__ __launch_bounds__(128) void k_mlp(
    const float* __restrict__ pre_feat,
    const float* __restrict__ W_sp,
    const float* __restrict__ b_sp,
    const float* __restrict__ W_t,
    const float* __restrict__ b_t,
    const float* __restrict__ W_o,
    const float* __restrict__ b_o,
    float*       __restrict__ d_out)
{
    __shared__ float4 sW[CIN * 6];
    __shared__ float  sWt[CHID], sWo[CHID], sB[CHID];
    int t = threadIdx.x;
    const float4* Wv = reinterpret_cast<const float4*>(W_sp);
    for (int i = t; i < CIN * 6; i += 128) sW[i] = Wv[i];
    if (t < CHID) { sWt[t] = W_t[t]; sWo[t] = W_o[t]; sB[t] = b_sp[t]; }
    __syncthreads();

    double npos  = fmax(g_red[2], 1.0);
    double zmean = g_red[0] / npos;
    double var   = g_red[1] - zmean * zmean * npos;
    float  znorm = (float)sqrt(fmax(var, 0.0)) + 1e-5f;
    float  zmf   = (float)zmean;

    int p0 = blockIdx.x * 128 + t;   // handles points p0 + k*TQ, k=0..3

    u64 A01[CHID], A23[CHID];
#pragma unroll
    for (int j = 0; j < CHID; j++) {
        u64 bb = pack2(sB[j], sB[j]);
        A01[j] = bb; A23[j] = bb;
    }

    // features (channels 0..23)
    const float4* f0 = reinterpret_cast<const float4*>(g_features) + (size_t)p0 * 6;
    const float4* f1 = f0 + (size_t)TQ * 6;
    const float4* f2 = f1 + (size_t)TQ * 6;
    const float4* f3 = f2 + (size_t)TQ * 6;
#pragma unroll
    for (int j4 = 0; j4 < 6; j4++) {
        float4 F0 = f0[j4], F1 = f1[j4], F2 = f2[j4], F3 = f3[j4];
        mlp_row(A01, A23, pack2(F0.x, F1.x), pack2(F2.x, F3.x), sW + (4*j4+0)*6);
        mlp_row(A01, A23, pack2(F0.y, F1.y), pack2(F2.y, F3.y), sW + (4*j4+1)*6);
        mlp_row(A01, A23, pack2(F0.z, F1.z), pack2(F2.z, F3.z), sW + (4*j4+2)*6);
        mlp_row(A01, A23, pack2(F0.w, F1.w), pack2(F2.w, F3.w), sW + (4*j4+3)*6);
    }
    // zn (channel 24)
    {
        float z0 = g_z[p0], z1 = g_z[p0 + TQ], z2 = g_z[p0 + 2*TQ], z3 = g_z[p0 + 3*TQ];
        float n0 = (z0 > 0.f) ? (z0 - zmf) / znorm : 0.f;
        float n1 = (z1 > 0.f) ? (z1 - zmf) / znorm : 0.f;
        float n2 = (z2 > 0.f) ? (z2 - zmf) / znorm : 0.f;
        float n3 = (z3 > 0.f) ? (z3 - zmf) / znorm : 0.f;
        mlp_row(A01, A23, pack2(n0, n1), pack2(n2, n3), sW + NC * 6);
    }
    // pre_feat (channels 25..74)
    {
        const float2* q0 = reinterpret_cast<const float2*>(pre_feat + (size_t)( p0          >> 3) * CPRE);
        const float2* q1 = reinterpret_cast<const float2*>(pre_feat + (size_t)((p0 +   TQ) >> 3) * CPRE);
        const float2* q2 = reinterpret_cast<const float2*>(pre_feat + (size_t)((p0 + 2*TQ) >> 3) * CPRE);
        const float2* q3 = reinterpret_cast<const float2*>(pre_feat + (size_t)((p0 + 3*TQ) >> 3) * CPRE);
#pragma unroll
        for (int i = 0; i < CPRE / 2; i++) {
            float2 g0 = q0[i], g1 = q1[i], g2 = q2[i], g3 = q3[i];
            mlp_row(A01, A23, pack2(g0.x, g1.x), pack2(g2.x, g3.x), sW + (NC + 1 + 2*i + 0) * 6);
            mlp_row(A01, A23, pack2(g0.y, g1.y), pack2(g2.y, g3.y), sW + (NC + 1 + 2*i + 1) * 6);
        }
    }

    // relu + heads
    float bt = b_t[0], bo = b_o[0];
    float ts0 = bt, ts1 = bt, ts2 = bt, ts3 = bt;
    float oc0 = bo, oc1 = bo, oc2 = bo, oc3 = bo;
#pragma unroll
    for (int j = 0; j < CHID; j++) {
        float2 ab = unpack2(A01[j]);
        float2 cd = unpack2(A23[j]);
        float h0 = fmaxf(ab.x, 0.f), h1 = fmaxf(ab.y, 0.f);
        float h2 = fmaxf(cd.x, 0.f), h3 = fmaxf(cd.y, 0.f);
        float wt = sWt[j], wo = sWo[j];
        ts0 += h0 * wt; ts1 += h1 * wt; ts2 += h2 * wt; ts3 += h3 * wt;
        oc0 += h0 * wo; oc1 += h1 * wo; oc2 += h2 * wo; oc3 += h3 * wo;
    }
    float2* out = reinterpret_cast<float2*>(d_out);
    out[p0         ] = make_float2(ts0, oc0);
    out[p0 +   TQ  ] = make_float2(ts1, oc1);
    out[p0 + 2*TQ  ] = make_float2(ts2, oc2);
    out[p0 + 3*TQ  ] = make_float2(ts3, oc3);
}

// ---------------- launch ----------------
extern "C" void kernel_launch(void* const* d_in, const int* in_sizes, int n_in,
                              void* d_out, int out_size)
{
    const float *pre_feat = nullptr, *feats = nullptr, *KRcam = nullptr,
                *origin = nullptr, *w2ac = nullptr, *W_sp = nullptr,
                *b_sp = nullptr, *W_t = nullptr, *b_t = nullptr,
                *W_o = nullptr, *b_o = nullptr;
    const int* pre_coords = nullptr;
    int n24 = 0, n1 = 0;

    for (int i = 0; i < n_in; i++) {
        int s = in_sizes[i];
        const void* p = d_in[i];
        switch (s) {
            case MPTS * CPRE:  pre_feat   = (const float*)p; break;
            case MPTS * 4:     pre_coords = (const int*)p;   break;
            case VHW * NC:     feats      = (const float*)p; break;
            case NV * 16:      KRcam      = (const float*)p; break;
            case 3:            origin     = (const float*)p; break;
            case 16:           w2ac       = (const float*)p; break;
            case CIN * CHID:   W_sp       = (const float*)p; break;
            case 24:
                if (n24 == 0) b_sp = (const float*)p;
                else if (n24 == 1) W_t = (const float*)p;
                else W_o = (const float*)p;
                n24++; break;
            case 1:
                if (n1 == 0) b_t = (const float*)p;
                else b_o = (const float*)p;
                n1++; break;
            default: break;
        }
    }

    k_transpose<<<(VHW * 3 + 255) / 256, 256>>>(feats);
    k_backproject<<<NPTS / 256, 256>>>(pre_coords, KRcam, origin, w2ac, (float*)d_out);
    k_mlp<<<TQ / 128, 128>>>(pre_feat, W_sp, b_sp, W_t, b_t, W_o, b_o, (float*)d_out);
}